// round 4
// baseline (speedup 1.0000x reference)
#include <cuda_runtime.h>
#include <cstdint>

// Problem constants (fixed shapes from reference)
#define BB 4
#define HH 224
#define WW 224
#define CC 16
#define FF 32
#define HO 220
#define WO 220

// Channel-planar u8 scratch: P[b][c][h][w]  (3.2 MB, static device global — allowed)
__device__ unsigned char g_planar[BB * CC * HH * WW];

__device__ __forceinline__ int dp4a_us(unsigned a, unsigned b, int c) {
    int d;
    asm("dp4a.u32.s32 %0, %1, %2, %3;" : "=r"(d) : "r"(a), "r"(b), "r"(c));
    return d;
}

// -------------------------------------------------------------------------
// Prepass: NHWC fp32 -> planar u8, smem-transposed so reads AND writes coalesce.
// One block per (b, h) row: reads 224*16 floats contiguously, writes 16 rows
// of 224 bytes as u32 words.
// -------------------------------------------------------------------------
__global__ __launch_bounds__(256) void prepass_kernel(const float* __restrict__ in) {
    __shared__ unsigned char sm[CC][WW];
    int bh = blockIdx.x;
    int b = bh / HH, h = bh % HH;
    const float* row = in + (size_t)(b * HH + h) * WW * CC;

    for (int l = threadIdx.x; l < WW * CC; l += 256) {
        int w = l >> 4, c = l & 15;             // l = w*16 + c (contiguous read)
        sm[c][w] = (unsigned char)(int)row[l];
    }
    __syncthreads();

    unsigned* dst = (unsigned*)g_planar;
    for (int l = threadIdx.x; l < CC * (WW / 4); l += 256) {
        int c = l / (WW / 4), g = l % (WW / 4);
        unsigned v = (unsigned)sm[c][4 * g]
                   | ((unsigned)sm[c][4 * g + 1] << 8)
                   | ((unsigned)sm[c][4 * g + 2] << 16)
                   | ((unsigned)sm[c][4 * g + 3] << 24);
        dst[((b * CC + c) * HH + h) * (WW / 4) + g] = v;
    }
}

// -------------------------------------------------------------------------
// Main conv kernel.
// grid.x = B*HO*2. block = 512 threads: warp = channel c, lane = filter f.
// Each thread produces out[b][ho][c][f][wo0..wo0+3] per iteration (STG.128).
//
// Vertical packing: V[col] = u8x4(x[ho+0..ho+3][col]).  Row 4 handled with
// horizontally packed bytes + byte-shifted kernel words -> 7 dp4a / output.
// -------------------------------------------------------------------------
__global__ __launch_bounds__(512, 2) void conv_main_kernel(
    const float* __restrict__ kern, float* __restrict__ out)
{
    __shared__ unsigned char rows[5][CC][WW];             // 17920 B
    __shared__ __align__(16) unsigned Vsm[CC][WW];        // 14336 B

    int bid = blockIdx.x;
    int half = bid & 1;
    int t = bid >> 1;
    int ho = t % HO;
    int b = t / HO;
    int tid = threadIdx.x;
    int c = tid >> 5;        // warp id = channel (16 warps, 16 channels)
    int f = tid & 31;        // lane = filter

    // ---- Stage 5 planar rows (u32 vector loads, fully coalesced) ----
    const unsigned* P = (const unsigned*)g_planar;
    unsigned* rows32 = (unsigned*)rows;
    for (int l = tid; l < 5 * CC * (WW / 4); l += 512) {
        int r = l / (CC * (WW / 4));
        int rem = l - r * (CC * (WW / 4));
        int cc = rem / (WW / 4);
        int g = rem - cc * (WW / 4);
        rows32[(r * CC + cc) * (WW / 4) + g] =
            P[((b * CC + cc) * HH + ho + r) * (WW / 4) + g];
    }
    __syncthreads();

    // ---- Build vertical packed words V[c][w] = rows0..3 bytes ----
    for (int l = tid; l < CC * WW; l += 512) {
        int cc = l / WW, w = l - cc * WW;
        Vsm[cc][w] = (unsigned)rows[0][cc][w]
                   | ((unsigned)rows[1][cc][w] << 8)
                   | ((unsigned)rows[2][cc][w] << 16)
                   | ((unsigned)rows[3][cc][w] << 24);
    }

    // ---- Load & pack weights for this (c, f) — coalesced across lanes ----
    int kk[5][5];
#pragma unroll
    for (int i = 0; i < 5; i++)
#pragma unroll
        for (int j = 0; j < 5; j++)
            kk[i][j] = (int)kern[((i * 5 + j) * CC + c) * FF + f];

    unsigned Kv[5];
#pragma unroll
    for (int j = 0; j < 5; j++)
        Kv[j] = ((unsigned)(kk[0][j] & 0xFF))
              | ((unsigned)(kk[1][j] & 0xFF) << 8)
              | ((unsigned)(kk[2][j] & 0xFF) << 16)
              | ((unsigned)(kk[3][j] & 0xFF) << 24);

    unsigned K4 = ((unsigned)(kk[4][0] & 0xFF))
                | ((unsigned)(kk[4][1] & 0xFF) << 8)
                | ((unsigned)(kk[4][2] & 0xFF) << 16)
                | ((unsigned)(kk[4][3] & 0xFF) << 24);
    unsigned k44 = (unsigned)(kk[4][4] & 0xFF);

    // Byte-shifted row-4 kernel words: contribution(s) = dp4a(ra, lo[s]) + dp4a(rb, hi[s])
    unsigned lo[4], hi[4];
    lo[0] = K4;              hi[0] = k44;
    lo[1] = K4 << 8;         hi[1] = (K4 >> 24) | (k44 << 8);
    lo[2] = K4 << 16;        hi[2] = (K4 >> 16) | (k44 << 16);
    lo[3] = K4 << 24;        hi[3] = (K4 >> 8)  | (k44 << 24);

    __syncthreads();

    int g0 = half ? 28 : 0;
    int g1 = half ? 55 : 28;

    const unsigned* Vrow = &Vsm[c][0];
    const unsigned* R4   = (const unsigned*)&rows[4][c][0];
    float* obase = out + ((((size_t)b * HO + ho) * CC + c) * FF + f) * WO;

    uint4 va = *(const uint4*)(Vrow + 4 * g0);  // cols wo0..wo0+3
    unsigned ra = R4[g0];                        // row4 bytes wo0..wo0+3

    for (int g = g0; g < g1; ++g) {
        uint4 vb = *(const uint4*)(Vrow + 4 * g + 4);  // cols wo0+4..wo0+7 (broadcast LDS.128)
        unsigned rb = R4[g + 1];

        // s = 0 : cols wo0 .. wo0+4
        int a0 = dp4a_us(va.x, Kv[0], 0);
        a0 = dp4a_us(va.y, Kv[1], a0);
        a0 = dp4a_us(va.z, Kv[2], a0);
        a0 = dp4a_us(va.w, Kv[3], a0);
        a0 = dp4a_us(vb.x, Kv[4], a0);
        a0 = dp4a_us(ra, lo[0], a0);
        a0 = dp4a_us(rb, hi[0], a0);
        // s = 1
        int a1 = dp4a_us(va.y, Kv[0], 0);
        a1 = dp4a_us(va.z, Kv[1], a1);
        a1 = dp4a_us(va.w, Kv[2], a1);
        a1 = dp4a_us(vb.x, Kv[3], a1);
        a1 = dp4a_us(vb.y, Kv[4], a1);
        a1 = dp4a_us(ra, lo[1], a1);
        a1 = dp4a_us(rb, hi[1], a1);
        // s = 2
        int a2 = dp4a_us(va.z, Kv[0], 0);
        a2 = dp4a_us(va.w, Kv[1], a2);
        a2 = dp4a_us(vb.x, Kv[2], a2);
        a2 = dp4a_us(vb.y, Kv[3], a2);
        a2 = dp4a_us(vb.z, Kv[4], a2);
        a2 = dp4a_us(ra, lo[2], a2);
        a2 = dp4a_us(rb, hi[2], a2);
        // s = 3
        int a3 = dp4a_us(va.w, Kv[0], 0);
        a3 = dp4a_us(vb.x, Kv[1], a3);
        a3 = dp4a_us(vb.y, Kv[2], a3);
        a3 = dp4a_us(vb.z, Kv[3], a3);
        a3 = dp4a_us(vb.w, Kv[4], a3);
        a3 = dp4a_us(ra, lo[3], a3);
        a3 = dp4a_us(rb, hi[3], a3);

        float4 o = make_float4((float)a0, (float)a1, (float)a2, (float)a3);
        *(float4*)(obase + 4 * g) = o;

        va = vb;
        ra = rb;
    }
}

// -------------------------------------------------------------------------
// kernel_launch: prepass + main conv. Graph-capturable: 2 launches, no sync,
// no allocation (scratch is a static __device__ array).
// -------------------------------------------------------------------------
extern "C" void kernel_launch(void* const* d_in, const int* in_sizes, int n_in,
                              void* d_out, int out_size) {
    const float* inputs = (const float*)d_in[0];  // [4,224,224,16] f32
    const float* kernel = (const float*)d_in[1];  // [5,5,16,32]    f32
    float* out = (float*)d_out;                   // [4,220,16,32,220] f32

    prepass_kernel<<<BB * HH, 256>>>(inputs);
    conv_main_kernel<<<BB * HO * 2, 512>>>(kernel, out);
}

// round 8
// speedup vs baseline: 2.1353x; 2.1353x over previous
#include <cuda_runtime.h>
#include <cstdint>

// Problem constants (fixed shapes)
#define BB 4
#define HH 224
#define WW 224
#define CC 16
#define FF 32
#define HO 220
#define WO 220
#define WG (WW / 4)   // 56 u32 words per planar row

// Channel-planar u8 scratch: P[b][c][h][w] (3.2 MB static device global)
__device__ unsigned char g_planar[BB * CC * HH * WW];

__device__ __forceinline__ int dp4a_us(unsigned a, unsigned b, int c) {
    int d;
    asm("dp4a.u32.s32 %0, %1, %2, %3;" : "=r"(d) : "r"(a), "r"(b), "r"(c));
    return d;
}

// Exact int->float for |x| < 2^22 using the magic-constant trick (IADD+FADD,
// avoids the conversion pipe). Accumulators are bounded by 255*8*25 < 2^17.
__device__ __forceinline__ float i2f_fast(int x) {
    return __int_as_float(0x4B400000 + x) - 12582912.0f;
}

// -------------------------------------------------------------------------
// Prepass: NHWC fp32 -> planar u8, smem-transposed so reads AND writes coalesce.
// -------------------------------------------------------------------------
__global__ __launch_bounds__(256) void prepass_kernel(const float* __restrict__ in) {
    __shared__ unsigned char sm[CC][WW];
    int bh = blockIdx.x;
    int b = bh / HH, h = bh % HH;
    const float* row = in + (size_t)(b * HH + h) * WW * CC;

    for (int l = threadIdx.x; l < WW * CC; l += 256) {
        int w = l >> 4, c = l & 15;             // l = w*16 + c (contiguous read)
        sm[c][w] = (unsigned char)(int)row[l];
    }
    __syncthreads();

    unsigned* dst = (unsigned*)g_planar;
    for (int l = threadIdx.x; l < CC * WG; l += 256) {
        int c = l / WG, g = l % WG;
        unsigned v = (unsigned)sm[c][4 * g]
                   | ((unsigned)sm[c][4 * g + 1] << 8)
                   | ((unsigned)sm[c][4 * g + 2] << 16)
                   | ((unsigned)sm[c][4 * g + 3] << 24);
        dst[((b * CC + c) * HH + h) * WG + g] = v;
    }
}

// -------------------------------------------------------------------------
// Main conv kernel.
// grid.x = B*HO (880 blocks). 512 threads = 16 warps. warp = channel c.
// For each f, lane = wo-group: lane l computes out[b][ho][c][f][4g..4g+3]
// with g = l (+32 on pass 2). STG.128 is fully coalesced (512B/warp-store).
//
// V[c][col] = u8x4 of input rows ho..ho+3 at col (vertical packing) -> 5 dp4a.
// Row ho+4 via horizontally packed bytes + byte-shifted kernel words -> 2 dp4a.
// -------------------------------------------------------------------------
__global__ __launch_bounds__(512, 2) void conv_main_kernel(
    const float* __restrict__ kern, float* __restrict__ out)
{
    __shared__ __align__(16) unsigned Vsm[CC][WW];   // 14336 B
    __shared__ unsigned R4sm[CC][WG];                // 3584 B
    __shared__ unsigned Wsm[7][CC * FF];             // 14336 B  (total 32256 B)

    int bid = blockIdx.x;
    int ho = bid % HO;
    int b = bid / HO;
    int tid = threadIdx.x;
    int c = tid >> 5;       // warp id = channel
    int lane = tid & 31;

    // ---- Pack weights into smem: pair p = tid = c*32 + f (coalesced reads) ----
    {
        int kk[25];
#pragma unroll
        for (int t = 0; t < 25; t++)
            kk[t] = (int)kern[t * (CC * FF) + tid];   // ((i*5+j)*CC + c)*FF + f
#pragma unroll
        for (int j = 0; j < 5; j++) {
            unsigned kv = ((unsigned)(kk[j] & 0xFF))
                        | ((unsigned)(kk[5 + j] & 0xFF) << 8)
                        | ((unsigned)(kk[10 + j] & 0xFF) << 16)
                        | ((unsigned)(kk[15 + j] & 0xFF) << 24);
            Wsm[j][tid] = kv;
        }
        unsigned K4 = ((unsigned)(kk[20] & 0xFF))
                    | ((unsigned)(kk[21] & 0xFF) << 8)
                    | ((unsigned)(kk[22] & 0xFF) << 16)
                    | ((unsigned)(kk[23] & 0xFF) << 24);
        Wsm[5][tid] = K4;
        Wsm[6][tid] = (unsigned)(kk[24] & 0xFF);
    }

    // ---- Stage input: load 5 planar rows, byte-transpose rows 0..3 into V ----
    const unsigned* P = (const unsigned*)g_planar;
    for (int l = tid; l < CC * WG; l += 512) {
        int cc = l / WG, g = l % WG;
        const unsigned* base = P + ((size_t)(b * CC + cc) * HH + ho) * WG + g;
        unsigned w0 = base[0 * WG];
        unsigned w1 = base[1 * WG];
        unsigned w2 = base[2 * WG];
        unsigned w3 = base[3 * WG];
        unsigned w4 = base[4 * WG];
        // 4x4 byte transpose via 8 PRMT
        unsigned t0 = __byte_perm(w0, w1, 0x5140);
        unsigned t1 = __byte_perm(w0, w1, 0x7362);
        unsigned t2 = __byte_perm(w2, w3, 0x5140);
        unsigned t3 = __byte_perm(w2, w3, 0x7362);
        uint4 v;
        v.x = __byte_perm(t0, t2, 0x5410);
        v.y = __byte_perm(t0, t2, 0x7632);
        v.z = __byte_perm(t1, t3, 0x5410);
        v.w = __byte_perm(t1, t3, 0x7632);
        *(uint4*)&Vsm[cc][4 * g] = v;    // STS.128, conflict-free
        R4sm[cc][g] = w4;
    }
    __syncthreads();

    const unsigned* Vrow = &Vsm[c][0];
    const unsigned* R4 = &R4sm[c][0];
    float* rowbase = out + ((size_t)(b * HO + ho) * CC + c) * FF * WO;
    const int pbase = c * 32;   // weight-table base for this warp's channel

#pragma unroll
    for (int pass = 0; pass < 2; pass++) {
        int g = lane + pass * 32;
        bool act = (g < 55);                 // 55 float4 groups cover WO=220
        uint4 va, vb;
        unsigned ra, rb;
        if (act) {
            va = *(const uint4*)(Vrow + 4 * g);       // cols 4g..4g+3
            vb = *(const uint4*)(Vrow + 4 * g + 4);   // cols 4g+4..4g+7
            ra = R4[g];
            rb = R4[g + 1];
        }
        float* pb = rowbase + 4 * g;

        for (int ff = 0; ff < 32; ff++) {
            // Broadcast weight fetch for (c, ff)
            unsigned Kv0 = Wsm[0][pbase + ff];
            unsigned Kv1 = Wsm[1][pbase + ff];
            unsigned Kv2 = Wsm[2][pbase + ff];
            unsigned Kv3 = Wsm[3][pbase + ff];
            unsigned Kv4 = Wsm[4][pbase + ff];
            unsigned K4  = Wsm[5][pbase + ff];
            unsigned k44 = Wsm[6][pbase + ff];

            if (act) {
                // s = 0 : cols 4g .. 4g+4
                int a0 = dp4a_us(va.x, Kv0, 0);
                a0 = dp4a_us(va.y, Kv1, a0);
                a0 = dp4a_us(va.z, Kv2, a0);
                a0 = dp4a_us(va.w, Kv3, a0);
                a0 = dp4a_us(vb.x, Kv4, a0);
                a0 = dp4a_us(ra, K4, a0);
                a0 = dp4a_us(rb, k44, a0);
                // s = 1
                int a1 = dp4a_us(va.y, Kv0, 0);
                a1 = dp4a_us(va.z, Kv1, a1);
                a1 = dp4a_us(va.w, Kv2, a1);
                a1 = dp4a_us(vb.x, Kv3, a1);
                a1 = dp4a_us(vb.y, Kv4, a1);
                a1 = dp4a_us(ra, K4 << 8, a1);
                a1 = dp4a_us(rb, (K4 >> 24) | (k44 << 8), a1);
                // s = 2
                int a2 = dp4a_us(va.z, Kv0, 0);
                a2 = dp4a_us(va.w, Kv1, a2);
                a2 = dp4a_us(vb.x, Kv2, a2);
                a2 = dp4a_us(vb.y, Kv3, a2);
                a2 = dp4a_us(vb.z, Kv4, a2);
                a2 = dp4a_us(ra, K4 << 16, a2);
                a2 = dp4a_us(rb, (K4 >> 16) | (k44 << 16), a2);
                // s = 3
                int a3 = dp4a_us(va.w, Kv0, 0);
                a3 = dp4a_us(vb.x, Kv1, a3);
                a3 = dp4a_us(vb.y, Kv2, a3);
                a3 = dp4a_us(vb.z, Kv3, a3);
                a3 = dp4a_us(vb.w, Kv4, a3);
                a3 = dp4a_us(ra, K4 << 24, a3);
                a3 = dp4a_us(rb, (K4 >> 8) | (k44 << 24), a3);

                float4 o = make_float4(i2f_fast(a0), i2f_fast(a1),
                                       i2f_fast(a2), i2f_fast(a3));
                *(float4*)(pb + ff * WO) = o;   // coalesced: 512B per warp-store
            }
        }
    }
}

// -------------------------------------------------------------------------
// kernel_launch: prepass + main conv. Graph-capturable: 2 launches, no sync,
// no allocation (scratch is a static __device__ array).
// -------------------------------------------------------------------------
extern "C" void kernel_launch(void* const* d_in, const int* in_sizes, int n_in,
                              void* d_out, int out_size) {
    const float* inputs = (const float*)d_in[0];  // [4,224,224,16] f32
    const float* kernel = (const float*)d_in[1];  // [5,5,16,32]    f32
    float* out = (float*)d_out;                   // [4,220,16,32,220] f32

    prepass_kernel<<<BB * HH, 256>>>(inputs);
    conv_main_kernel<<<BB * HO, 512>>>(kernel, out);
}